// round 2
// baseline (speedup 1.0000x reference)
#include <cuda_runtime.h>
#include <math.h>

// Problem constants (fixed by reference setup_inputs)
#define B_BATCH 512
#define T_SEQ   256
#define D_IN    512
#define H_DIM   1024
#define K_TOT   (H_DIM + D_IN)   // 1536: fused [h | x_t] @ [U ; W]

// Double-buffered hidden state scratch (4 MB) — device global, no allocations.
__device__ float g_h[2][B_BATCH * H_DIM];

// ---------------------------------------------------------------------------
// Zero the initial hidden state (must run every kernel_launch call: scratch
// persists across graph replays and the launch must be deterministic).
// ---------------------------------------------------------------------------
__global__ void zero_h0_kernel() {
    int i = blockIdx.x * blockDim.x + threadIdx.x;
    g_h[0][i] = 0.0f;
}

// ---------------------------------------------------------------------------
// One recurrent step as a fused GEMM:
//   h_out[b, n] = tanh( sum_{k<1024} h_in[b,k]*U[k,n]
//                     + sum_{d<512}  x[b,t,d]*W[d,n]  + bias[n] )
// M=512 (batch), N=1024 (hidden), K=1536.
// BM=BN=64, BK=16, 256 threads, 4x4 microtile -> grid 16x8 = 128 CTAs (1 wave).
// ---------------------------------------------------------------------------
#define BM 64
#define BN 64
#define BK 16

__global__ __launch_bounds__(256) void rnn_step_kernel(
    const float* __restrict__ x,     // [B, T, D]
    const float* __restrict__ W,     // [D, H]
    const float* __restrict__ U,     // [H, H]
    const float* __restrict__ bias,  // [H]
    int t, int parity)
{
    const float* __restrict__ h_in = g_h[parity];
    float* __restrict__ h_out      = g_h[parity ^ 1];

    __shared__ __align__(16) float As[BK][BM + 4];  // transposed A tile, padded
    __shared__ __align__(16) float Bs[BK][BN];

    const int tid  = threadIdx.x;
    const int row0 = blockIdx.y * BM;   // batch-row block
    const int col0 = blockIdx.x * BN;   // hidden-col block

    // A-tile load mapping: 64 rows x 16 k, one float4 along k per thread
    const int arow  = tid >> 2;          // 0..63
    const int akoff = (tid & 3) * 4;     // 0,4,8,12
    // B-tile load mapping: 16 k-rows x 64 n, one float4 along n per thread
    const int brow = tid >> 4;           // 0..15
    const int bcol = (tid & 15) * 4;     // 0..60

    // Compute mapping: 16x16 threads, 4x4 outputs each
    const int tx = tid & 15;
    const int ty = tid >> 4;

    float acc[4][4];
#pragma unroll
    for (int i = 0; i < 4; i++)
#pragma unroll
        for (int j = 0; j < 4; j++) acc[i][j] = 0.0f;

    for (int k0 = 0; k0 < K_TOT; k0 += BK) {
        // ---- load A tile (h_in for k<1024, x[:,t,:] for k>=1024) ----
        {
            const int kg = k0 + akoff;
            float4 av;
            if (kg < H_DIM) {
                av = *reinterpret_cast<const float4*>(
                        &h_in[(size_t)(row0 + arow) * H_DIM + kg]);
            } else {
                av = *reinterpret_cast<const float4*>(
                        &x[(size_t)(row0 + arow) * T_SEQ * D_IN
                           + (size_t)t * D_IN + (kg - H_DIM)]);
            }
            const int kk = akoff;
            As[kk + 0][arow] = av.x;
            As[kk + 1][arow] = av.y;
            As[kk + 2][arow] = av.z;
            As[kk + 3][arow] = av.w;
        }
        // ---- load B tile (U for k<1024, W for k>=1024) ----
        {
            const int kg = k0 + brow;
            float4 bv;
            if (kg < H_DIM) {
                bv = *reinterpret_cast<const float4*>(
                        &U[(size_t)kg * H_DIM + col0 + bcol]);
            } else {
                bv = *reinterpret_cast<const float4*>(
                        &W[(size_t)(kg - H_DIM) * H_DIM + col0 + bcol]);
            }
            *reinterpret_cast<float4*>(&Bs[brow][bcol]) = bv;
        }
        __syncthreads();

#pragma unroll
        for (int k = 0; k < BK; k++) {
            const float4 a = *reinterpret_cast<const float4*>(&As[k][ty * 4]);
            const float4 b = *reinterpret_cast<const float4*>(&Bs[k][tx * 4]);
            acc[0][0] += a.x * b.x; acc[0][1] += a.x * b.y;
            acc[0][2] += a.x * b.z; acc[0][3] += a.x * b.w;
            acc[1][0] += a.y * b.x; acc[1][1] += a.y * b.y;
            acc[1][2] += a.y * b.z; acc[1][3] += a.y * b.w;
            acc[2][0] += a.z * b.x; acc[2][1] += a.z * b.y;
            acc[2][2] += a.z * b.z; acc[2][3] += a.z * b.w;
            acc[3][0] += a.w * b.x; acc[3][1] += a.w * b.y;
            acc[3][2] += a.w * b.z; acc[3][3] += a.w * b.w;
        }
        __syncthreads();
    }

    // ---- epilogue: bias + tanh ----
#pragma unroll
    for (int i = 0; i < 4; i++) {
        const int row = row0 + ty * 4 + i;
#pragma unroll
        for (int j = 0; j < 4; j++) {
            const int col = col0 + tx * 4 + j;
            h_out[(size_t)row * H_DIM + col] = tanhf(acc[i][j] + bias[col]);
        }
    }
}

// ---------------------------------------------------------------------------
// Final Dense(1): logits[b] = h_last[b,:] . Wd + bd
// One block (256 threads) per batch row; h_last lives in g_h[0]
// (step t reads parity t&1, writes t&1^1 -> last write (t=255) lands in g_h[0]).
// ---------------------------------------------------------------------------
__global__ __launch_bounds__(256) void final_dense_kernel(
    const float* __restrict__ Wd,   // [H, 1]
    const float* __restrict__ bd,   // [1]
    float* __restrict__ out)        // [B, 1]
{
    __shared__ float red[256];
    const int b   = blockIdx.x;
    const int tid = threadIdx.x;
    const float* __restrict__ h = g_h[0];

    float s = 0.0f;
#pragma unroll
    for (int i = tid; i < H_DIM; i += 256)
        s += h[(size_t)b * H_DIM + i] * Wd[i];

    red[tid] = s;
    __syncthreads();
    for (int off = 128; off > 0; off >>= 1) {
        if (tid < off) red[tid] += red[tid + off];
        __syncthreads();
    }
    if (tid == 0) out[b] = red[0] + bd[0];
}

// ---------------------------------------------------------------------------
// kernel_launch: graph-capturable, allocation-free.
// ---------------------------------------------------------------------------
extern "C" void kernel_launch(void* const* d_in, const int* in_sizes, int n_in,
                              void* d_out, int out_size)
{
    const float* x    = (const float*)d_in[0];   // [512, 256, 512]
    const float* W    = (const float*)d_in[1];   // [512, 1024]
    const float* U    = (const float*)d_in[2];   // [1024, 1024]
    const float* bias = (const float*)d_in[3];   // [1024]
    const float* Wd   = (const float*)d_in[4];   // [1024, 1]
    const float* bd   = (const float*)d_in[5];   // [1]
    float* out        = (float*)d_out;           // [512, 1]

    // h0 = 0
    zero_h0_kernel<<<(B_BATCH * H_DIM) / 256, 256>>>();

    // 256 sequential recurrent steps (captured as 256 graph nodes)
    dim3 grid(H_DIM / BN, B_BATCH / BM);  // (16, 8) = 128 CTAs
    for (int t = 0; t < T_SEQ; t++) {
        rnn_step_kernel<<<grid, 256>>>(x, W, U, bias, t, t & 1);
    }

    // logits = h_last @ Wd + bd
    final_dense_kernel<<<B_BATCH, 256>>>(Wd, bd, out);
}

// round 7
// speedup vs baseline: 3.8299x; 3.8299x over previous
#include <cuda_runtime.h>
#include <cuda_bf16.h>
#include <math.h>
#include <stdint.h>

// Problem constants
#define B_BATCH 512
#define T_SEQ   256
#define D_IN    512
#define H_DIM   1024

// ---------------------------------------------------------------------------
// Device scratch (static globals — no allocations)
// ---------------------------------------------------------------------------
__device__ __align__(16) __nv_bfloat16 g_hhi[2][B_BATCH * H_DIM];   // 1 MB x2
__device__ __align__(16) __nv_bfloat16 g_hlo[2][B_BATCH * H_DIM];
__device__ __align__(16) __nv_bfloat16 g_Ut_hi[H_DIM * H_DIM];      // 2 MB
__device__ __align__(16) __nv_bfloat16 g_Ut_lo[H_DIM * H_DIM];
__device__ __align__(16) __nv_bfloat16 g_Wt_hi[H_DIM * D_IN];       // 1 MB
__device__ __align__(16) __nv_bfloat16 g_Wt_lo[H_DIM * D_IN];
__device__ __align__(16) float g_xw[(size_t)T_SEQ * B_BATCH * H_DIM]; // [t][b][h] 512 MB

// ---------------------------------------------------------------------------
// Helpers (all baseline PTX, no sm_103a-only features)
// ---------------------------------------------------------------------------
static __device__ __forceinline__ uint32_t smem_u32(const void* p) {
    uint32_t a;
    asm("{ .reg .u64 t; cvta.to.shared.u64 t, %1; cvt.u32.u64 %0, t; }"
        : "=r"(a) : "l"(p));
    return a;
}
static __device__ __forceinline__ void cp16(uint32_t dst, const void* src) {
    asm volatile("cp.async.cg.shared.global [%0], [%1], 16;" :: "r"(dst), "l"(src));
}
static __device__ __forceinline__ void cp_commit() {
    asm volatile("cp.async.commit_group;" ::: "memory");
}
template <int N> static __device__ __forceinline__ void cp_wait() {
    asm volatile("cp.async.wait_group %0;" :: "n"(N) : "memory");
}
static __device__ __forceinline__ void ldsm4(uint32_t* r, uint32_t a) {
    asm volatile("ldmatrix.sync.aligned.m8n8.x4.shared.b16 {%0,%1,%2,%3}, [%4];"
                 : "=r"(r[0]), "=r"(r[1]), "=r"(r[2]), "=r"(r[3]) : "r"(a));
}
static __device__ __forceinline__ void mma16816(float* d, const uint32_t* a,
                                                uint32_t b0, uint32_t b1) {
    asm volatile(
        "mma.sync.aligned.m16n8k16.row.col.f32.bf16.bf16.f32 "
        "{%0,%1,%2,%3}, {%4,%5,%6,%7}, {%8,%9}, {%0,%1,%2,%3};"
        : "+f"(d[0]), "+f"(d[1]), "+f"(d[2]), "+f"(d[3])
        : "r"(a[0]), "r"(a[1]), "r"(a[2]), "r"(a[3]), "r"(b0), "r"(b1));
}
static __device__ __forceinline__ uint32_t pack2bf(float a, float b) {
    __nv_bfloat16 ha = __float2bfloat16(a), hb = __float2bfloat16(b);
    return (uint32_t)__bfloat16_as_ushort(ha) |
           ((uint32_t)__bfloat16_as_ushort(hb) << 16);
}

// ---------------------------------------------------------------------------
// Prep: transpose + split fp32 weight [K][1024] -> bf16 hi/lo [1024][K]
// which: 0 -> W (K=512) into g_Wt, 1 -> U (K=1024) into g_Ut
// ---------------------------------------------------------------------------
__global__ __launch_bounds__(256) void transpose_split_kernel(
    const float* __restrict__ src, int K, int which)
{
    __shared__ float tile[32][33];
    __nv_bfloat16* dhi = which ? g_Ut_hi : g_Wt_hi;
    __nv_bfloat16* dlo = which ? g_Ut_lo : g_Wt_lo;
    const int kb = blockIdx.x * 32;
    const int nb = blockIdx.y * 32;
    const int tx = threadIdx.x & 31;
    const int wy = threadIdx.x >> 5;
#pragma unroll
    for (int i = 0; i < 4; i++)
        tile[wy + i * 8][tx] = src[(size_t)(kb + wy + i * 8) * H_DIM + nb + tx];
    __syncthreads();
#pragma unroll
    for (int i = 0; i < 4; i++) {
        const int n = nb + wy + i * 8;
        const float v = tile[tx][wy + i * 8];
        __nv_bfloat16 hi = __float2bfloat16(v);
        __nv_bfloat16 lo = __float2bfloat16(v - __bfloat162float(hi));
        dhi[(size_t)n * K + kb + tx] = hi;
        dlo[(size_t)n * K + kb + tx] = lo;
    }
}

__global__ __launch_bounds__(256) void zero_h_kernel() {
    const int i = blockIdx.x * 256 + threadIdx.x;   // < 65536 uint4
    reinterpret_cast<uint4*>(g_hhi[0])[i] = make_uint4(0, 0, 0, 0);
    reinterpret_cast<uint4*>(g_hlo[0])[i] = make_uint4(0, 0, 0, 0);
}

// ---------------------------------------------------------------------------
// Precompute XW[t][b][h] = x[b][t][:] @ W + bias   (split-bf16, 3 passes)
// Grid: 2048 CTAs, each owns 64 consecutive rows of x (row = b*256 + t)
// and loops the 16 n-groups, keeping its full A-slice (64x512 hi+lo) in smem.
// ---------------------------------------------------------------------------
#define PA_STR   1040                      // 512 bf16 (1024B) + 16B pad
#define PA_LO    66560                     // 64 * 1040
#define PB_OFF   133120                    // A region total (hi+lo)
#define PB_STG   10240                     // B stage: hi 5120 + lo 5120
#define PSMEM    (PB_OFF + 2 * PB_STG)     // 153600

__global__ __launch_bounds__(256) void xw_kernel(
    const float* __restrict__ x, const float* __restrict__ bias)
{
    extern __shared__ __align__(16) char ps[];
    const uint32_t sb = smem_u32(ps);
    const int tid  = threadIdx.x;
    const int lane = tid & 31;
    const int wid  = tid >> 5;
    const int wm   = (wid >> 2) * 32;     // warp m origin (0/32)
    const int wn   = (wid & 3) * 16;      // warp n origin (0/16/32/48)
    const int row0 = blockIdx.x * 64;     // global x-row group

    // ---- phase 1: load 64 x-rows (fp32) and split into smem hi/lo ----
#pragma unroll
    for (int i = 0; i < 32; i++) {
        const int u4 = tid + i * 256;           // 8192 float4-units
        const int r  = u4 >> 7, u = u4 & 127;
        const float4 v = *reinterpret_cast<const float4*>(
            &x[(size_t)(row0 + r) * D_IN + u * 4]);
        const float hx = __bfloat162float(__float2bfloat16(v.x));
        const float hy = __bfloat162float(__float2bfloat16(v.y));
        const float hz = __bfloat162float(__float2bfloat16(v.z));
        const float hw = __bfloat162float(__float2bfloat16(v.w));
        *reinterpret_cast<uint2*>(ps + r * PA_STR + u * 8) =
            make_uint2(pack2bf(v.x, v.y), pack2bf(v.z, v.w));
        *reinterpret_cast<uint2*>(ps + PA_LO + r * PA_STR + u * 8) =
            make_uint2(pack2bf(v.x - hx, v.y - hy), pack2bf(v.z - hz, v.w - hw));
    }
    __syncthreads();

    const int crow = tid >> 2, cu = tid & 3;          // B cp.async mapping
    const uint32_t bdst  = crow * 80 + cu * 16;
    const uint32_t aoff  = (lane & 15) * PA_STR + (lane >> 4) * 16;
    const uint32_t boff  = (lane & 7) * 80 + (lane >> 3) * 16;

    for (int ng = 0; ng < 16; ng++) {
        const int col0 = ng * 64;
        const __nv_bfloat16* srcBh = g_Wt_hi + (size_t)(col0 + crow) * D_IN + cu * 8;
        const __nv_bfloat16* srcBl = g_Wt_lo + (size_t)(col0 + crow) * D_IN + cu * 8;

        float acc[2][2][4];
#pragma unroll
        for (int a = 0; a < 2; a++)
#pragma unroll
            for (int b = 0; b < 2; b++)
#pragma unroll
                for (int q = 0; q < 4; q++) acc[a][b][q] = 0.0f;

        // prologue
        cp16(sb + PB_OFF + bdst,        srcBh);
        cp16(sb + PB_OFF + 5120 + bdst, srcBl);
        cp_commit();

        for (int c = 0; c < 16; c++) {
            const int s = c & 1;
            if (c + 1 < 16) {
                const uint32_t st = sb + PB_OFF + (s ^ 1) * PB_STG;
                cp16(st + bdst,        srcBh + (c + 1) * 32);
                cp16(st + 5120 + bdst, srcBl + (c + 1) * 32);
                cp_commit();
                cp_wait<1>();
            } else {
                cp_wait<0>();
            }
            __syncthreads();

            const uint32_t stB = sb + PB_OFF + s * PB_STG;
            uint32_t ah[2][2][4], al[2][2][4], bh[2][4], bl[2][4];
#pragma unroll
            for (int mt = 0; mt < 2; mt++)
#pragma unroll
                for (int kt = 0; kt < 2; kt++) {
                    const uint32_t a0 = sb + (wm + mt * 16) * PA_STR
                                      + c * 64 + kt * 32 + aoff;
                    ldsm4(ah[mt][kt], a0);
                    ldsm4(al[mt][kt], a0 + PA_LO);
                }
#pragma unroll
            for (int nt = 0; nt < 2; nt++) {
                const uint32_t b0 = stB + (wn + nt * 8) * 80 + boff;
                ldsm4(bh[nt], b0);
                ldsm4(bl[nt], b0 + 5120);
            }
#pragma unroll
            for (int kt = 0; kt < 2; kt++)
#pragma unroll
                for (int mt = 0; mt < 2; mt++)
#pragma unroll
                    for (int nt = 0; nt < 2; nt++) {
                        mma16816(acc[mt][nt], ah[mt][kt], bh[nt][kt*2], bh[nt][kt*2+1]);
                        mma16816(acc[mt][nt], ah[mt][kt], bl[nt][kt*2], bl[nt][kt*2+1]);
                        mma16816(acc[mt][nt], al[mt][kt], bh[nt][kt*2], bh[nt][kt*2+1]);
                    }
            __syncthreads();
        }

        // epilogue: XW[t][b][h] = acc + bias   (row = b*256 + t)
#pragma unroll
        for (int mt = 0; mt < 2; mt++)
#pragma unroll
            for (int nt = 0; nt < 2; nt++) {
                const int cidx = col0 + wn + nt * 8 + (lane & 3) * 2;
                const float bz0 = bias[cidx], bz1 = bias[cidx + 1];
#pragma unroll
                for (int half = 0; half < 2; half++) {
                    const int rg = row0 + wm + mt * 16 + (lane >> 2) + half * 8;
                    const int bb = rg >> 8, tt = rg & 255;
                    float2 o;
                    o.x = acc[mt][nt][half * 2 + 0] + bz0;
                    o.y = acc[mt][nt][half * 2 + 1] + bz1;
                    *reinterpret_cast<float2*>(
                        &g_xw[((size_t)tt * B_BATCH + bb) * H_DIM + cidx]) = o;
                }
            }
    }
}

// ---------------------------------------------------------------------------
// One recurrent step: h_out = tanh( h_in @ U  + XW[t] )
// M=512, N=1024, K=1024. BM=BN=64, BK=32 -> grid (16,8)=128 CTAs, 256 thr.
// Split-bf16, 3 passes, cp.async double-buffered, ldmatrix + mma.sync.
// ---------------------------------------------------------------------------
#define SSTG 20480   // stage: Ahi 5120 | Alo 5120 | Bhi 5120 | Blo 5120

__global__ __launch_bounds__(256) void rnn_step_kernel(int t, int parity)
{
    __shared__ __align__(16) char smem[2 * SSTG];
    const uint32_t sb = smem_u32(smem);
    const int tid  = threadIdx.x;
    const int lane = tid & 31;
    const int wid  = tid >> 5;
    const int wm   = (wid >> 2) * 32;
    const int wn   = (wid & 3) * 16;
    const int col0 = blockIdx.x * 64;
    const int row0 = blockIdx.y * 64;

    const int crow = tid >> 2, cu = tid & 3;
    const uint32_t dst = crow * 80 + cu * 16;
    const __nv_bfloat16* srcAh = g_hhi[parity] + (size_t)(row0 + crow) * H_DIM + cu * 8;
    const __nv_bfloat16* srcAl = g_hlo[parity] + (size_t)(row0 + crow) * H_DIM + cu * 8;
    const __nv_bfloat16* srcBh = g_Ut_hi + (size_t)(col0 + crow) * H_DIM + cu * 8;
    const __nv_bfloat16* srcBl = g_Ut_lo + (size_t)(col0 + crow) * H_DIM + cu * 8;

    const uint32_t aoff = (lane & 15) * 80 + (lane >> 4) * 16;
    const uint32_t boff = (lane & 7) * 80 + (lane >> 3) * 16;

    float acc[2][2][4];
#pragma unroll
    for (int a = 0; a < 2; a++)
#pragma unroll
        for (int b = 0; b < 2; b++)
#pragma unroll
            for (int q = 0; q < 4; q++) acc[a][b][q] = 0.0f;

    // prologue: chunk 0 into stage 0
    {
        const uint32_t st = sb;
        cp16(st + dst,         srcAh);
        cp16(st + 5120 + dst,  srcAl);
        cp16(st + 10240 + dst, srcBh);
        cp16(st + 15360 + dst, srcBl);
        cp_commit();
    }

    for (int c = 0; c < 32; c++) {
        const int s = c & 1;
        if (c + 1 < 32) {
            const uint32_t st = sb + (s ^ 1) * SSTG;
            const int kb = (c + 1) * 32;
            cp16(st + dst,         srcAh + kb);
            cp16(st + 5120 + dst,  srcAl + kb);
            cp16(st + 10240 + dst, srcBh + kb);
            cp16(st + 15360 + dst, srcBl + kb);
            cp_commit();
            cp_wait<1>();
        } else {
            cp_wait<0>();
        }
        __syncthreads();

        const uint32_t st = sb + s * SSTG;
        uint32_t ah[2][2][4], al[2][2][4], bh[2][4], bl[2][4];
#pragma unroll
        for (int mt = 0; mt < 2; mt++)
#pragma unroll
            for (int kt = 0; kt < 2; kt++) {
                const uint32_t a0 = st + (wm + mt * 16) * 80 + kt * 32 + aoff;
                ldsm4(ah[mt][kt], a0);
                ldsm4(al[mt][kt], a0 + 5120);
            }
#pragma unroll
        for (int nt = 0; nt < 2; nt++) {
            const uint32_t b0 = st + 10240 + (wn + nt * 8) * 80 + boff;
            ldsm4(bh[nt], b0);
            ldsm4(bl[nt], b0 + 5120);
        }
#pragma unroll
        for (int kt = 0; kt < 2; kt++)
#pragma unroll
            for (int mt = 0; mt < 2; mt++)
#pragma unroll
                for (int nt = 0; nt < 2; nt++) {
                    mma16816(acc[mt][nt], ah[mt][kt], bh[nt][kt*2], bh[nt][kt*2+1]);
                    mma16816(acc[mt][nt], ah[mt][kt], bl[nt][kt*2], bl[nt][kt*2+1]);
                    mma16816(acc[mt][nt], al[mt][kt], bh[nt][kt*2], bh[nt][kt*2+1]);
                }
        __syncthreads();
    }

    // epilogue: + XW[t], tanh, split to bf16 hi/lo
    __nv_bfloat16* oh = g_hhi[parity ^ 1];
    __nv_bfloat16* ol = g_hlo[parity ^ 1];
#pragma unroll
    for (int mt = 0; mt < 2; mt++)
#pragma unroll
        for (int nt = 0; nt < 2; nt++) {
            const int cidx = col0 + wn + nt * 8 + (lane & 3) * 2;
#pragma unroll
            for (int half = 0; half < 2; half++) {
                const int r = row0 + wm + mt * 16 + (lane >> 2) + half * 8;
                const float2 xw = *reinterpret_cast<const float2*>(
                    &g_xw[((size_t)t * B_BATCH + r) * H_DIM + cidx]);
                const float v0 = tanhf(acc[mt][nt][half * 2 + 0] + xw.x);
                const float v1 = tanhf(acc[mt][nt][half * 2 + 1] + xw.y);
                const float h0 = __bfloat162float(__float2bfloat16(v0));
                const float h1 = __bfloat162float(__float2bfloat16(v1));
                *reinterpret_cast<uint32_t*>(&oh[(size_t)r * H_DIM + cidx]) =
                    pack2bf(v0, v1);
                *reinterpret_cast<uint32_t*>(&ol[(size_t)r * H_DIM + cidx]) =
                    pack2bf(v0 - h0, v1 - h1);
            }
        }
}

// ---------------------------------------------------------------------------
// Final Dense(1): out[b] = (hhi+hlo)[0][b,:] . Wd + bd
// ---------------------------------------------------------------------------
__global__ __launch_bounds__(256) void final_dense_kernel(
    const float* __restrict__ Wd, const float* __restrict__ bd,
    float* __restrict__ out)
{
    __shared__ float red[256];
    const int b = blockIdx.x, tid = threadIdx.x;
    float s = 0.0f;
#pragma unroll
    for (int i = tid; i < H_DIM; i += 256) {
        const float h = __bfloat162float(g_hhi[0][(size_t)b * H_DIM + i])
                      + __bfloat162float(g_hlo[0][(size_t)b * H_DIM + i]);
        s += h * Wd[i];
    }
    red[tid] = s;
    __syncthreads();
    for (int off = 128; off > 0; off >>= 1) {
        if (tid < off) red[tid] += red[tid + off];
        __syncthreads();
    }
    if (tid == 0) out[b] = red[0] + bd[0];
}

// ---------------------------------------------------------------------------
extern "C" void kernel_launch(void* const* d_in, const int* in_sizes, int n_in,
                              void* d_out, int out_size)
{
    const float* x    = (const float*)d_in[0];   // [512, 256, 512]
    const float* W    = (const float*)d_in[1];   // [512, 1024]
    const float* U    = (const float*)d_in[2];   // [1024, 1024]
    const float* bias = (const float*)d_in[3];   // [1024]
    const float* Wd   = (const float*)d_in[4];   // [1024, 1]
    const float* bd   = (const float*)d_in[5];   // [1]
    float* out        = (float*)d_out;           // [512, 1]

    cudaFuncSetAttribute(xw_kernel,
                         cudaFuncAttributeMaxDynamicSharedMemorySize, PSMEM);

    // prep: transposed+split weights, zero h0
    transpose_split_kernel<<<dim3(D_IN / 32, H_DIM / 32), 256>>>(W, D_IN, 0);
    transpose_split_kernel<<<dim3(H_DIM / 32, H_DIM / 32), 256>>>(U, H_DIM, 1);
    zero_h_kernel<<<256, 256>>>();

    // XW = x @ W + b  (one big parallel tensor GEMM)
    xw_kernel<<<(B_BATCH * T_SEQ) / 64, 256, PSMEM>>>(x, bias);

    // 256 sequential recurrent steps
    dim3 grid(H_DIM / 64, B_BATCH / 64);   // (16, 8) = 128 CTAs
    for (int t = 0; t < T_SEQ; t++) {
        rnn_step_kernel<<<grid, 256>>>(t, t & 1);
    }

    final_dense_kernel<<<B_BATCH, 256>>>(Wd, bd, out);
}

// round 8
// speedup vs baseline: 4.6527x; 1.2148x over previous
#include <cuda_runtime.h>
#include <cuda_bf16.h>
#include <math.h>
#include <stdint.h>

// Problem constants
#define B_BATCH 512
#define T_SEQ   256
#define D_IN    512
#define H_DIM   1024

// ---------------------------------------------------------------------------
// Device scratch (static globals — no allocations)
// ---------------------------------------------------------------------------
__device__ __align__(16) __nv_bfloat16 g_hhi[2][B_BATCH * H_DIM];   // 1 MB x2
__device__ __align__(16) __nv_bfloat16 g_hlo[2][B_BATCH * H_DIM];
__device__ __align__(16) __nv_bfloat16 g_Ut_hi[H_DIM * H_DIM];      // 2 MB
__device__ __align__(16) __nv_bfloat16 g_Ut_lo[H_DIM * H_DIM];
__device__ __align__(16) __nv_bfloat16 g_Wt_hi[H_DIM * D_IN];       // 1 MB
__device__ __align__(16) __nv_bfloat16 g_Wt_lo[H_DIM * D_IN];
__device__ __align__(16) float g_xw[(size_t)T_SEQ * B_BATCH * H_DIM]; // [t][b][h] 512 MB
__device__ int g_bar[8];   // per-row-group step barriers

// ---------------------------------------------------------------------------
// Helpers (all baseline PTX, no sm_103a-only features)
// ---------------------------------------------------------------------------
static __device__ __forceinline__ uint32_t smem_u32(const void* p) {
    uint32_t a;
    asm("{ .reg .u64 t; cvta.to.shared.u64 t, %1; cvt.u32.u64 %0, t; }"
        : "=r"(a) : "l"(p));
    return a;
}
static __device__ __forceinline__ void cp16(uint32_t dst, const void* src) {
    asm volatile("cp.async.cg.shared.global [%0], [%1], 16;" :: "r"(dst), "l"(src));
}
static __device__ __forceinline__ void cp_commit() {
    asm volatile("cp.async.commit_group;" ::: "memory");
}
template <int N> static __device__ __forceinline__ void cp_wait() {
    asm volatile("cp.async.wait_group %0;" :: "n"(N) : "memory");
}
static __device__ __forceinline__ void ldsm4(uint32_t* r, uint32_t a) {
    asm volatile("ldmatrix.sync.aligned.m8n8.x4.shared.b16 {%0,%1,%2,%3}, [%4];"
                 : "=r"(r[0]), "=r"(r[1]), "=r"(r[2]), "=r"(r[3]) : "r"(a));
}
static __device__ __forceinline__ void mma16816(float* d, const uint32_t* a,
                                                uint32_t b0, uint32_t b1) {
    asm volatile(
        "mma.sync.aligned.m16n8k16.row.col.f32.bf16.bf16.f32 "
        "{%0,%1,%2,%3}, {%4,%5,%6,%7}, {%8,%9}, {%0,%1,%2,%3};"
        : "+f"(d[0]), "+f"(d[1]), "+f"(d[2]), "+f"(d[3])
        : "r"(a[0]), "r"(a[1]), "r"(a[2]), "r"(a[3]), "r"(b0), "r"(b1));
}
static __device__ __forceinline__ uint32_t pack2bf(float a, float b) {
    __nv_bfloat16 ha = __float2bfloat16(a), hb = __float2bfloat16(b);
    return (uint32_t)__bfloat16_as_ushort(ha) |
           ((uint32_t)__bfloat16_as_ushort(hb) << 16);
}

// ---------------------------------------------------------------------------
// Prep: transpose + split fp32 weight [K][1024] -> bf16 hi/lo [1024][K]
// ---------------------------------------------------------------------------
__global__ __launch_bounds__(256) void transpose_split_kernel(
    const float* __restrict__ src, int K, int which)
{
    __shared__ float tile[32][33];
    __nv_bfloat16* dhi = which ? g_Ut_hi : g_Wt_hi;
    __nv_bfloat16* dlo = which ? g_Ut_lo : g_Wt_lo;
    const int kb = blockIdx.x * 32;
    const int nb = blockIdx.y * 32;
    const int tx = threadIdx.x & 31;
    const int wy = threadIdx.x >> 5;
#pragma unroll
    for (int i = 0; i < 4; i++)
        tile[wy + i * 8][tx] = src[(size_t)(kb + wy + i * 8) * H_DIM + nb + tx];
    __syncthreads();
#pragma unroll
    for (int i = 0; i < 4; i++) {
        const int n = nb + wy + i * 8;
        const float v = tile[tx][wy + i * 8];
        __nv_bfloat16 hi = __float2bfloat16(v);
        __nv_bfloat16 lo = __float2bfloat16(v - __bfloat162float(hi));
        dhi[(size_t)n * K + kb + tx] = hi;
        dlo[(size_t)n * K + kb + tx] = lo;
    }
}

__global__ __launch_bounds__(256) void zero_h_kernel() {
    const int i = blockIdx.x * 256 + threadIdx.x;   // < 65536 uint4
    reinterpret_cast<uint4*>(g_hhi[0])[i] = make_uint4(0, 0, 0, 0);
    reinterpret_cast<uint4*>(g_hlo[0])[i] = make_uint4(0, 0, 0, 0);
    if (blockIdx.x == 0 && threadIdx.x < 8) g_bar[threadIdx.x] = 0;
}

// ---------------------------------------------------------------------------
// Precompute XW[t][b][h] = x[b][t][:] @ W + bias   (split-bf16, 3 passes)
// (unchanged from round 7 — verified working)
// ---------------------------------------------------------------------------
#define PA_STR   1040
#define PA_LO    66560
#define PB_OFF   133120
#define PB_STG   10240
#define PSMEM    (PB_OFF + 2 * PB_STG)

__global__ __launch_bounds__(256) void xw_kernel(
    const float* __restrict__ x, const float* __restrict__ bias)
{
    extern __shared__ __align__(16) char ps[];
    const uint32_t sb = smem_u32(ps);
    const int tid  = threadIdx.x;
    const int lane = tid & 31;
    const int wid  = tid >> 5;
    const int wm   = (wid >> 2) * 32;
    const int wn   = (wid & 3) * 16;
    const int row0 = blockIdx.x * 64;

#pragma unroll
    for (int i = 0; i < 32; i++) {
        const int u4 = tid + i * 256;
        const int r  = u4 >> 7, u = u4 & 127;
        const float4 v = *reinterpret_cast<const float4*>(
            &x[(size_t)(row0 + r) * D_IN + u * 4]);
        const float hx = __bfloat162float(__float2bfloat16(v.x));
        const float hy = __bfloat162float(__float2bfloat16(v.y));
        const float hz = __bfloat162float(__float2bfloat16(v.z));
        const float hw = __bfloat162float(__float2bfloat16(v.w));
        *reinterpret_cast<uint2*>(ps + r * PA_STR + u * 8) =
            make_uint2(pack2bf(v.x, v.y), pack2bf(v.z, v.w));
        *reinterpret_cast<uint2*>(ps + PA_LO + r * PA_STR + u * 8) =
            make_uint2(pack2bf(v.x - hx, v.y - hy), pack2bf(v.z - hz, v.w - hw));
    }
    __syncthreads();

    const int crow = tid >> 2, cu = tid & 3;
    const uint32_t bdst  = crow * 80 + cu * 16;
    const uint32_t aoff  = (lane & 15) * PA_STR + (lane >> 4) * 16;
    const uint32_t boff  = (lane & 7) * 80 + (lane >> 3) * 16;

    for (int ng = 0; ng < 16; ng++) {
        const int col0 = ng * 64;
        const __nv_bfloat16* srcBh = g_Wt_hi + (size_t)(col0 + crow) * D_IN + cu * 8;
        const __nv_bfloat16* srcBl = g_Wt_lo + (size_t)(col0 + crow) * D_IN + cu * 8;

        float acc[2][2][4];
#pragma unroll
        for (int a = 0; a < 2; a++)
#pragma unroll
            for (int b = 0; b < 2; b++)
#pragma unroll
                for (int q = 0; q < 4; q++) acc[a][b][q] = 0.0f;

        cp16(sb + PB_OFF + bdst,        srcBh);
        cp16(sb + PB_OFF + 5120 + bdst, srcBl);
        cp_commit();

        for (int c = 0; c < 16; c++) {
            const int s = c & 1;
            if (c + 1 < 16) {
                const uint32_t st = sb + PB_OFF + (s ^ 1) * PB_STG;
                cp16(st + bdst,        srcBh + (c + 1) * 32);
                cp16(st + 5120 + bdst, srcBl + (c + 1) * 32);
                cp_commit();
                cp_wait<1>();
            } else {
                cp_wait<0>();
            }
            __syncthreads();

            const uint32_t stB = sb + PB_OFF + s * PB_STG;
            uint32_t ah[2][2][4], al[2][2][4], bh[2][4], bl[2][4];
#pragma unroll
            for (int mt = 0; mt < 2; mt++)
#pragma unroll
                for (int kt = 0; kt < 2; kt++) {
                    const uint32_t a0 = sb + (wm + mt * 16) * PA_STR
                                      + c * 64 + kt * 32 + aoff;
                    ldsm4(ah[mt][kt], a0);
                    ldsm4(al[mt][kt], a0 + PA_LO);
                }
#pragma unroll
            for (int nt = 0; nt < 2; nt++) {
                const uint32_t b0 = stB + (wn + nt * 8) * 80 + boff;
                ldsm4(bh[nt], b0);
                ldsm4(bl[nt], b0 + 5120);
            }
#pragma unroll
            for (int kt = 0; kt < 2; kt++)
#pragma unroll
                for (int mt = 0; mt < 2; mt++)
#pragma unroll
                    for (int nt = 0; nt < 2; nt++) {
                        mma16816(acc[mt][nt], ah[mt][kt], bh[nt][kt*2], bh[nt][kt*2+1]);
                        mma16816(acc[mt][nt], ah[mt][kt], bl[nt][kt*2], bl[nt][kt*2+1]);
                        mma16816(acc[mt][nt], al[mt][kt], bh[nt][kt*2], bh[nt][kt*2+1]);
                    }
            __syncthreads();
        }

#pragma unroll
        for (int mt = 0; mt < 2; mt++)
#pragma unroll
            for (int nt = 0; nt < 2; nt++) {
                const int cidx = col0 + wn + nt * 8 + (lane & 3) * 2;
                const float bz0 = bias[cidx], bz1 = bias[cidx + 1];
#pragma unroll
                for (int half = 0; half < 2; half++) {
                    const int rg = row0 + wm + mt * 16 + (lane >> 2) + half * 8;
                    const int bb = rg >> 8, tt = rg & 255;
                    float2 o;
                    o.x = acc[mt][nt][half * 2 + 0] + bz0;
                    o.y = acc[mt][nt][half * 2 + 1] + bz1;
                    *reinterpret_cast<float2*>(
                        &g_xw[((size_t)tt * B_BATCH + bb) * H_DIM + cidx]) = o;
                }
            }
    }
}

// ---------------------------------------------------------------------------
// Persistent recurrent kernel: all 256 steps in one launch.
// 128 CTAs (bx>>4 = row-group r, bx&15 = col-group c), 512 threads.
// Per step: h_out[64x64 tile] = tanh(h_in[64,1024] @ Ut[64,1024]^T + XW[t]).
// BK=64 chunks, 4-stage cp.async ring, one __syncthreads per chunk.
// Cross-step sync: per-row-group 16-CTA barrier on g_bar[r].
// ---------------------------------------------------------------------------
#define SROW 144                     // 128B chunk row + 16B pad
#define AHI  0
#define ALO  9216
#define BHI  18432
#define BLO  27648
#define SST  36864                   // bytes per stage
#define SMEM_P (4 * SST)             // 147456

__global__ __launch_bounds__(512) void rnn_persist_kernel()
{
    extern __shared__ __align__(16) char smem[];
    const uint32_t sb = smem_u32(smem);
    const int tid  = threadIdx.x;
    const int lane = tid & 31;
    const int wid  = tid >> 5;
    const int wm   = (wid >> 2) * 16;      // 4 m-groups
    const int wn   = (wid & 3) * 16;       // 4 n-groups
    const int rg   = blockIdx.x >> 4;      // row group 0..7
    const int row0 = rg * 64;
    const int col0 = (blockIdx.x & 15) * 64;

    // cp.async mapping: 512 threads x 16B per tensor per chunk
    const int arow = tid >> 3;             // 0..63
    const int au   = tid & 7;              // 16B unit within 128B row
    const uint32_t dsto = (uint32_t)arow * SROW + au * 16;

    const __nv_bfloat16* __restrict__ Bh =
        g_Ut_hi + (size_t)(col0 + arow) * H_DIM + au * 8;
    const __nv_bfloat16* __restrict__ Bl =
        g_Ut_lo + (size_t)(col0 + arow) * H_DIM + au * 8;

    const uint32_t aoff = (lane & 15) * SROW + (lane >> 4) * 16;
    const uint32_t boff = (lane & 7) * SROW + (lane >> 3) * 16;

    for (int t = 0; t < T_SEQ; t++) {
        if (t > 0) {
            if (tid == 0) {
                const int target = 16 * t;
                while (*((volatile int*)&g_bar[rg]) < target) { }
            }
            __syncthreads();
            __threadfence();
        }

        const int pin = t & 1;
        const __nv_bfloat16* __restrict__ Ah =
            g_hhi[pin] + (size_t)(row0 + arow) * H_DIM + au * 8;
        const __nv_bfloat16* __restrict__ Al =
            g_hlo[pin] + (size_t)(row0 + arow) * H_DIM + au * 8;

        // prefetch xw values for this thread's outputs
        float2 xwv[2][2];
#pragma unroll
        for (int nt = 0; nt < 2; nt++) {
            const int cidx = col0 + wn + nt * 8 + (lane & 3) * 2;
#pragma unroll
            for (int half = 0; half < 2; half++) {
                const int r = row0 + wm + (lane >> 2) + half * 8;
                xwv[nt][half] = *reinterpret_cast<const float2*>(
                    &g_xw[((size_t)t * B_BATCH + r) * H_DIM + cidx]);
            }
        }

        // prologue: chunks 0..2 into stages 0..2
#pragma unroll
        for (int p = 0; p < 3; p++) {
            const uint32_t st = sb + p * SST;
            const int kb = p * 64;
            cp16(st + AHI + dsto, Ah + kb);
            cp16(st + ALO + dsto, Al + kb);
            cp16(st + BHI + dsto, Bh + kb);
            cp16(st + BLO + dsto, Bl + kb);
            cp_commit();
        }

        float acc[2][4];
#pragma unroll
        for (int nt = 0; nt < 2; nt++)
#pragma unroll
            for (int q = 0; q < 4; q++) acc[nt][q] = 0.0f;

        for (int c = 0; c < 16; c++) {
            cp_wait<2>();
            __syncthreads();

            // issue chunk c+3 into stage (c+3)&3 (safe: its readers done)
            if (c + 3 < 16) {
                const uint32_t st = sb + ((c + 3) & 3) * SST;
                const int kb = (c + 3) * 64;
                cp16(st + AHI + dsto, Ah + kb);
                cp16(st + ALO + dsto, Al + kb);
                cp16(st + BHI + dsto, Bh + kb);
                cp16(st + BLO + dsto, Bl + kb);
            }
            cp_commit();   // empty group at tail keeps wait counts valid

            const uint32_t st = sb + (c & 3) * SST;
            uint32_t ah[4][4], al[4][4], bh[2][2][4], bl[2][2][4];
#pragma unroll
            for (int kt = 0; kt < 4; kt++) {
                const uint32_t a0 = st + wm * SROW + kt * 32 + aoff;
                ldsm4(ah[kt], a0 + AHI);
                ldsm4(al[kt], a0 + ALO);
            }
#pragma unroll
            for (int nt = 0; nt < 2; nt++)
#pragma unroll
                for (int kb2 = 0; kb2 < 2; kb2++) {
                    const uint32_t b0 = st + (wn + nt * 8) * SROW + kb2 * 64 + boff;
                    ldsm4(bh[nt][kb2], b0 + BHI);
                    ldsm4(bl[nt][kb2], b0 + BLO);
                }
#pragma unroll
            for (int kt = 0; kt < 4; kt++) {
                const int kb2 = kt >> 1, pr = (kt & 1) * 2;
#pragma unroll
                for (int nt = 0; nt < 2; nt++) {
                    mma16816(acc[nt], ah[kt], bh[nt][kb2][pr], bh[nt][kb2][pr + 1]);
                    mma16816(acc[nt], ah[kt], bl[nt][kb2][pr], bl[nt][kb2][pr + 1]);
                    mma16816(acc[nt], al[kt], bh[nt][kb2][pr], bh[nt][kb2][pr + 1]);
                }
            }
        }

        // epilogue: + XW[t], tanh, split to bf16 hi/lo, store
        __nv_bfloat16* __restrict__ oh = g_hhi[pin ^ 1];
        __nv_bfloat16* __restrict__ ol = g_hlo[pin ^ 1];
#pragma unroll
        for (int nt = 0; nt < 2; nt++) {
            const int cidx = col0 + wn + nt * 8 + (lane & 3) * 2;
#pragma unroll
            for (int half = 0; half < 2; half++) {
                const int r = row0 + wm + (lane >> 2) + half * 8;
                const float v0 = tanhf(acc[nt][half * 2 + 0] + xwv[nt][half].x);
                const float v1 = tanhf(acc[nt][half * 2 + 1] + xwv[nt][half].y);
                const float h0 = __bfloat162float(__float2bfloat16(v0));
                const float h1 = __bfloat162float(__float2bfloat16(v1));
                *reinterpret_cast<uint32_t*>(&oh[(size_t)r * H_DIM + cidx]) =
                    pack2bf(v0, v1);
                *reinterpret_cast<uint32_t*>(&ol[(size_t)r * H_DIM + cidx]) =
                    pack2bf(v0 - h0, v1 - h1);
            }
        }

        if (t < T_SEQ - 1) {
            __threadfence();
            __syncthreads();
            if (tid == 0) atomicAdd(&g_bar[rg], 1);
        }
    }
}

// ---------------------------------------------------------------------------
// Final Dense(1): out[b] = (hhi+hlo)[0][b,:] . Wd + bd
// ---------------------------------------------------------------------------
__global__ __launch_bounds__(256) void final_dense_kernel(
    const float* __restrict__ Wd, const float* __restrict__ bd,
    float* __restrict__ out)
{
    __shared__ float red[256];
    const int b = blockIdx.x, tid = threadIdx.x;
    float s = 0.0f;
#pragma unroll
    for (int i = tid; i < H_DIM; i += 256) {
        const float h = __bfloat162float(g_hhi[0][(size_t)b * H_DIM + i])
                      + __bfloat162float(g_hlo[0][(size_t)b * H_DIM + i]);
        s += h * Wd[i];
    }
    red[tid] = s;
    __syncthreads();
    for (int off = 128; off > 0; off >>= 1) {
        if (tid < off) red[tid] += red[tid + off];
        __syncthreads();
    }
    if (tid == 0) out[b] = red[0] + bd[0];
}

// ---------------------------------------------------------------------------
extern "C" void kernel_launch(void* const* d_in, const int* in_sizes, int n_in,
                              void* d_out, int out_size)
{
    const float* x    = (const float*)d_in[0];   // [512, 256, 512]
    const float* W    = (const float*)d_in[1];   // [512, 1024]
    const float* U    = (const float*)d_in[2];   // [1024, 1024]
    const float* bias = (const float*)d_in[3];   // [1024]
    const float* Wd   = (const float*)d_in[4];   // [1024, 1]
    const float* bd   = (const float*)d_in[5];   // [1]
    float* out        = (float*)d_out;           // [512, 1]

    cudaFuncSetAttribute(xw_kernel,
                         cudaFuncAttributeMaxDynamicSharedMemorySize, PSMEM);
    cudaFuncSetAttribute(rnn_persist_kernel,
                         cudaFuncAttributeMaxDynamicSharedMemorySize, SMEM_P);

    // prep: transposed+split weights, zero h0 + barriers
    transpose_split_kernel<<<dim3(D_IN / 32, H_DIM / 32), 256>>>(W, D_IN, 0);
    transpose_split_kernel<<<dim3(H_DIM / 32, H_DIM / 32), 256>>>(U, H_DIM, 1);
    zero_h_kernel<<<256, 256>>>();

    // XW = x @ W + b  (one big parallel tensor GEMM)
    xw_kernel<<<(B_BATCH * T_SEQ) / 64, 256, PSMEM>>>(x, bias);

    // all 256 recurrent steps in ONE persistent launch
    rnn_persist_kernel<<<128, 512, SMEM_P>>>();

    final_dense_kernel<<<B_BATCH, 256>>>(Wd, bd, out);
}

// round 12
// speedup vs baseline: 5.5874x; 1.2009x over previous
#include <cuda_runtime.h>
#include <cuda_bf16.h>
#include <math.h>
#include <stdint.h>

// Problem constants
#define B_BATCH 512
#define T_SEQ   256
#define D_IN    512
#define H_DIM   1024

// ---------------------------------------------------------------------------
// Device scratch (static globals — no allocations)
// ---------------------------------------------------------------------------
__device__ __align__(16) __nv_bfloat16 g_hhi[2][B_BATCH * H_DIM];   // 1 MB x2
__device__ __align__(16) __nv_bfloat16 g_hlo[2][B_BATCH * H_DIM];
__device__ __align__(16) __nv_bfloat16 g_Ut_hi[H_DIM * H_DIM];      // 2 MB
__device__ __align__(16) __nv_bfloat16 g_Ut_lo[H_DIM * H_DIM];
__device__ __align__(16) __nv_bfloat16 g_Wt_hi[H_DIM * D_IN];       // 1 MB
__device__ __align__(16) __nv_bfloat16 g_Wt_lo[H_DIM * D_IN];
__device__ __align__(16) float g_xw[(size_t)T_SEQ * B_BATCH * H_DIM]; // [t][b][h] 512 MB
__device__ int g_bar[8];   // per-row-group step barriers

// ---------------------------------------------------------------------------
// Helpers (all baseline PTX, no sm_103a-only features)
// ---------------------------------------------------------------------------
static __device__ __forceinline__ uint32_t smem_u32(const void* p) {
    uint32_t a;
    asm("{ .reg .u64 t; cvta.to.shared.u64 t, %1; cvt.u32.u64 %0, t; }"
        : "=r"(a) : "l"(p));
    return a;
}
static __device__ __forceinline__ void cp16(uint32_t dst, const void* src) {
    asm volatile("cp.async.cg.shared.global [%0], [%1], 16;" :: "r"(dst), "l"(src));
}
static __device__ __forceinline__ void cp_commit() {
    asm volatile("cp.async.commit_group;" ::: "memory");
}
template <int N> static __device__ __forceinline__ void cp_wait() {
    asm volatile("cp.async.wait_group %0;" :: "n"(N) : "memory");
}
static __device__ __forceinline__ void ldsm4(uint32_t* r, uint32_t a) {
    asm volatile("ldmatrix.sync.aligned.m8n8.x4.shared.b16 {%0,%1,%2,%3}, [%4];"
                 : "=r"(r[0]), "=r"(r[1]), "=r"(r[2]), "=r"(r[3]) : "r"(a));
}
static __device__ __forceinline__ void mma16816(float* d, const uint32_t* a,
                                                uint32_t b0, uint32_t b1) {
    asm volatile(
        "mma.sync.aligned.m16n8k16.row.col.f32.bf16.bf16.f32 "
        "{%0,%1,%2,%3}, {%4,%5,%6,%7}, {%8,%9}, {%0,%1,%2,%3};"
        : "+f"(d[0]), "+f"(d[1]), "+f"(d[2]), "+f"(d[3])
        : "r"(a[0]), "r"(a[1]), "r"(a[2]), "r"(a[3]), "r"(b0), "r"(b1));
}
static __device__ __forceinline__ uint32_t pack2bf(float a, float b) {
    __nv_bfloat16 ha = __float2bfloat16(a), hb = __float2bfloat16(b);
    return (uint32_t)__bfloat16_as_ushort(ha) |
           ((uint32_t)__bfloat16_as_ushort(hb) << 16);
}
// pad-free 16B-unit swizzle: row stride 128B, unit col XOR (row&7)
#define SWZ(row, col) ((uint32_t)((row) * 128 + (((col) ^ ((row) & 7)) << 4)))

// ---------------------------------------------------------------------------
// Prep: transpose + split fp32 weight [K][1024] -> bf16 hi/lo [1024][K]
// ---------------------------------------------------------------------------
__global__ __launch_bounds__(256) void transpose_split_kernel(
    const float* __restrict__ src, int K, int which)
{
    __shared__ float tile[32][33];
    __nv_bfloat16* dhi = which ? g_Ut_hi : g_Wt_hi;
    __nv_bfloat16* dlo = which ? g_Ut_lo : g_Wt_lo;
    const int kb = blockIdx.x * 32;
    const int nb = blockIdx.y * 32;
    const int tx = threadIdx.x & 31;
    const int wy = threadIdx.x >> 5;
#pragma unroll
    for (int i = 0; i < 4; i++)
        tile[wy + i * 8][tx] = src[(size_t)(kb + wy + i * 8) * H_DIM + nb + tx];
    __syncthreads();
#pragma unroll
    for (int i = 0; i < 4; i++) {
        const int n = nb + wy + i * 8;
        const float v = tile[tx][wy + i * 8];
        __nv_bfloat16 hi = __float2bfloat16(v);
        __nv_bfloat16 lo = __float2bfloat16(v - __bfloat162float(hi));
        dhi[(size_t)n * K + kb + tx] = hi;
        dlo[(size_t)n * K + kb + tx] = lo;
    }
}

__global__ __launch_bounds__(256) void zero_h_kernel() {
    const int i = blockIdx.x * 256 + threadIdx.x;   // < 65536 uint4
    reinterpret_cast<uint4*>(g_hhi[0])[i] = make_uint4(0, 0, 0, 0);
    reinterpret_cast<uint4*>(g_hlo[0])[i] = make_uint4(0, 0, 0, 0);
    if (blockIdx.x == 0 && threadIdx.x < 8) g_bar[threadIdx.x] = 0;
}

// ---------------------------------------------------------------------------
// Precompute XW[t][b][h] = x[b][t][:] @ W + bias   (split-bf16, 3 passes)
// (verified in rounds 7/8 — unchanged)
// ---------------------------------------------------------------------------
#define PA_STR   1040
#define PA_LO    66560
#define PB_OFF   133120
#define PB_STG   10240
#define PSMEM    (PB_OFF + 2 * PB_STG)

__global__ __launch_bounds__(256) void xw_kernel(
    const float* __restrict__ x, const float* __restrict__ bias)
{
    extern __shared__ __align__(16) char ps[];
    const uint32_t sb = smem_u32(ps);
    const int tid  = threadIdx.x;
    const int lane = tid & 31;
    const int wid  = tid >> 5;
    const int wm   = (wid >> 2) * 32;
    const int wn   = (wid & 3) * 16;
    const int row0 = blockIdx.x * 64;

#pragma unroll
    for (int i = 0; i < 32; i++) {
        const int u4 = tid + i * 256;
        const int r  = u4 >> 7, u = u4 & 127;
        const float4 v = *reinterpret_cast<const float4*>(
            &x[(size_t)(row0 + r) * D_IN + u * 4]);
        const float hx = __bfloat162float(__float2bfloat16(v.x));
        const float hy = __bfloat162float(__float2bfloat16(v.y));
        const float hz = __bfloat162float(__float2bfloat16(v.z));
        const float hw = __bfloat162float(__float2bfloat16(v.w));
        *reinterpret_cast<uint2*>(ps + r * PA_STR + u * 8) =
            make_uint2(pack2bf(v.x, v.y), pack2bf(v.z, v.w));
        *reinterpret_cast<uint2*>(ps + PA_LO + r * PA_STR + u * 8) =
            make_uint2(pack2bf(v.x - hx, v.y - hy), pack2bf(v.z - hz, v.w - hw));
    }
    __syncthreads();

    const int crow = tid >> 2, cu = tid & 3;
    const uint32_t bdst  = crow * 80 + cu * 16;
    const uint32_t aoff  = (lane & 15) * PA_STR + (lane >> 4) * 16;
    const uint32_t boff  = (lane & 7) * 80 + (lane >> 3) * 16;

    for (int ng = 0; ng < 16; ng++) {
        const int col0 = ng * 64;
        const __nv_bfloat16* srcBh = g_Wt_hi + (size_t)(col0 + crow) * D_IN + cu * 8;
        const __nv_bfloat16* srcBl = g_Wt_lo + (size_t)(col0 + crow) * D_IN + cu * 8;

        float acc[2][2][4];
#pragma unroll
        for (int a = 0; a < 2; a++)
#pragma unroll
            for (int b = 0; b < 2; b++)
#pragma unroll
                for (int q = 0; q < 4; q++) acc[a][b][q] = 0.0f;

        cp16(sb + PB_OFF + bdst,        srcBh);
        cp16(sb + PB_OFF + 5120 + bdst, srcBl);
        cp_commit();

        for (int c = 0; c < 16; c++) {
            const int s = c & 1;
            if (c + 1 < 16) {
                const uint32_t st = sb + PB_OFF + (s ^ 1) * PB_STG;
                cp16(st + bdst,        srcBh + (c + 1) * 32);
                cp16(st + 5120 + bdst, srcBl + (c + 1) * 32);
                cp_commit();
                cp_wait<1>();
            } else {
                cp_wait<0>();
            }
            __syncthreads();

            const uint32_t stB = sb + PB_OFF + s * PB_STG;
            uint32_t ah[2][2][4], al[2][2][4], bh[2][4], bl[2][4];
#pragma unroll
            for (int mt = 0; mt < 2; mt++)
#pragma unroll
                for (int kt = 0; kt < 2; kt++) {
                    const uint32_t a0 = sb + (wm + mt * 16) * PA_STR
                                      + c * 64 + kt * 32 + aoff;
                    ldsm4(ah[mt][kt], a0);
                    ldsm4(al[mt][kt], a0 + PA_LO);
                }
#pragma unroll
            for (int nt = 0; nt < 2; nt++) {
                const uint32_t b0 = stB + (wn + nt * 8) * 80 + boff;
                ldsm4(bh[nt], b0);
                ldsm4(bl[nt], b0 + 5120);
            }
#pragma unroll
            for (int kt = 0; kt < 2; kt++)
#pragma unroll
                for (int mt = 0; mt < 2; mt++)
#pragma unroll
                    for (int nt = 0; nt < 2; nt++) {
                        mma16816(acc[mt][nt], ah[mt][kt], bh[nt][kt*2], bh[nt][kt*2+1]);
                        mma16816(acc[mt][nt], ah[mt][kt], bl[nt][kt*2], bl[nt][kt*2+1]);
                        mma16816(acc[mt][nt], al[mt][kt], bh[nt][kt*2], bh[nt][kt*2+1]);
                    }
            __syncthreads();
        }

#pragma unroll
        for (int mt = 0; mt < 2; mt++)
#pragma unroll
            for (int nt = 0; nt < 2; nt++) {
                const int cidx = col0 + wn + nt * 8 + (lane & 3) * 2;
                const float bz0 = bias[cidx], bz1 = bias[cidx + 1];
#pragma unroll
                for (int half = 0; half < 2; half++) {
                    const int rg = row0 + wm + mt * 16 + (lane >> 2) + half * 8;
                    const int bb = rg >> 8, tt = rg & 255;
                    float2 o;
                    o.x = acc[mt][nt][half * 2 + 0] + bz0;
                    o.y = acc[mt][nt][half * 2 + 1] + bz1;
                    *reinterpret_cast<float2*>(
                        &g_xw[((size_t)tt * B_BATCH + bb) * H_DIM + cidx]) = o;
                }
            }
    }
}

// ---------------------------------------------------------------------------
// Persistent recurrent kernel v2: 256 threads, warp tile 32x16,
// B_hi (U-slice) resident in smem all 256 steps, pad-free XOR swizzle,
// 4-stage ring streaming {A_hi, A_lo, B_lo}, one __syncthreads per chunk.
// Grid 128 CTAs: bx>>4 = row group (M), bx&15 = col group (N).
// ---------------------------------------------------------------------------
#define BHIP_SZ 131072                     // 16 chunks x 8192 B (64n x 64k bf16)
#define RST     24576                      // ring stage: Ahi 8K | Alo 8K | Blo 8K
#define SMEM_P  (BHIP_SZ + 4 * RST)        // 229376 <= 232448

__global__ __launch_bounds__(256) void rnn_persist_kernel()
{
    extern __shared__ __align__(16) char smem[];
    const uint32_t sb = smem_u32(smem);
    const int tid  = threadIdx.x;
    const int lane = tid & 31;
    const int wid  = tid >> 5;
    const int wm   = (wid >> 2) * 32;      // 2 m-positions (0,32)
    const int wn   = (wid & 3) * 16;       // 4 n-positions
    const int rg   = blockIdx.x >> 4;      // row group 0..7
    const int row0 = rg * 64;
    const int col0 = (blockIdx.x & 15) * 64;

    // ---- stream mapping: 256 threads, 2 x 16B units per tensor per chunk ----
    const int r1 = tid >> 3;               // rows r1 and r1+32
    const int c1 = tid & 7;                // 16B unit in 128B row
    const uint32_t o1 = SWZ(r1, c1);
    const uint32_t o2 = SWZ(r1 + 32, c1);

    const __nv_bfloat16* __restrict__ Bh1 =
        g_Ut_hi + (size_t)(col0 + r1) * H_DIM + c1 * 8;
    const __nv_bfloat16* __restrict__ Bh2 = Bh1 + (size_t)32 * H_DIM;
    const __nv_bfloat16* __restrict__ Bl1 =
        g_Ut_lo + (size_t)(col0 + r1) * H_DIM + c1 * 8;
    const __nv_bfloat16* __restrict__ Bl2 = Bl1 + (size_t)32 * H_DIM;

    // ---- fragment addressing (per-thread constants) ----
    const int arow = wm + (lane & 15);             // A row (mt adds 16)
    const uint32_t arowt0 = (uint32_t)arow * 128;
    const uint32_t arowt1 = (uint32_t)(arow + 16) * 128;
    const uint32_t swa = (uint32_t)(arow & 7);
    const int ua_lo = lane >> 4;                   // A unit low bit
    const uint32_t browt0 = (uint32_t)(wn + (lane & 7)) * 128;
    const uint32_t browt1 = (uint32_t)(wn + 8 + (lane & 7)) * 128;
    const uint32_t swb = (uint32_t)(lane & 7);
    const int ub_lo = lane >> 3;                   // B unit low bits (0..3)

    for (int t = 0; t < T_SEQ; t++) {
        if (t > 0) {
            if (tid == 0) {
                const int target = 16 * t;
                while (*((volatile int*)&g_bar[rg]) < target) { }
            }
            __syncthreads();
            __threadfence();
        }

        const int pin = t & 1;
        const __nv_bfloat16* __restrict__ Ah1 =
            g_hhi[pin] + (size_t)(row0 + r1) * H_DIM + c1 * 8;
        const __nv_bfloat16* __restrict__ Ah2 = Ah1 + (size_t)32 * H_DIM;
        const __nv_bfloat16* __restrict__ Al1 =
            g_hlo[pin] + (size_t)(row0 + r1) * H_DIM + c1 * 8;
        const __nv_bfloat16* __restrict__ Al2 = Al1 + (size_t)32 * H_DIM;

        // prefetch xw for this thread's outputs
        float2 xwv[2][2][2];
#pragma unroll
        for (int mt = 0; mt < 2; mt++)
#pragma unroll
            for (int nt = 0; nt < 2; nt++) {
                const int cidx = col0 + wn + nt * 8 + (lane & 3) * 2;
#pragma unroll
                for (int h8 = 0; h8 < 2; h8++) {
                    const int r = row0 + wm + mt * 16 + (lane >> 2) + h8 * 8;
                    xwv[mt][nt][h8] = *reinterpret_cast<const float2*>(
                        &g_xw[((size_t)t * B_BATCH + r) * H_DIM + cidx]);
                }
            }

        // one-time: load resident B_hi (16 chunks x 8K)
        if (t == 0) {
#pragma unroll
            for (int c = 0; c < 16; c++) {
                cp16(sb + c * 8192 + o1, Bh1 + c * 64);
                cp16(sb + c * 8192 + o2, Bh2 + c * 64);
            }
            cp_commit();
        }

        // prologue: chunks 0..2 into ring stages 0..2
#pragma unroll
        for (int p = 0; p < 3; p++) {
            const uint32_t st = sb + BHIP_SZ + p * RST;
            const int kb = p * 64;
            cp16(st + o1,         Ah1 + kb);
            cp16(st + o2,         Ah2 + kb);
            cp16(st + 8192 + o1,  Al1 + kb);
            cp16(st + 8192 + o2,  Al2 + kb);
            cp16(st + 16384 + o1, Bl1 + kb);
            cp16(st + 16384 + o2, Bl2 + kb);
            cp_commit();
        }

        float acc[2][2][4];
#pragma unroll
        for (int a = 0; a < 2; a++)
#pragma unroll
            for (int b = 0; b < 2; b++)
#pragma unroll
                for (int q = 0; q < 4; q++) acc[a][b][q] = 0.0f;

        for (int c = 0; c < 16; c++) {
            cp_wait<2>();
            __syncthreads();

            if (c + 3 < 16) {   // refill stage (c+3)&3 (its readers are done)
                const uint32_t st = sb + BHIP_SZ + ((c + 3) & 3) * RST;
                const int kb = (c + 3) * 64;
                cp16(st + o1,         Ah1 + kb);
                cp16(st + o2,         Ah2 + kb);
                cp16(st + 8192 + o1,  Al1 + kb);
                cp16(st + 8192 + o2,  Al2 + kb);
                cp16(st + 16384 + o1, Bl1 + kb);
                cp16(st + 16384 + o2, Bl2 + kb);
            }
            cp_commit();   // empty group at tail keeps wait counts valid

            const uint32_t sA   = sb + BHIP_SZ + (c & 3) * RST;
            const uint32_t sBhi = sb + c * 8192;
            const uint32_t sBlo = sA + 16384;

#pragma unroll
            for (int kb2 = 0; kb2 < 2; kb2++) {
                uint32_t bh[2][4], bl[2][4];
                const uint32_t ub = (uint32_t)(kb2 * 4 + ub_lo);
#pragma unroll
                for (int nt = 0; nt < 2; nt++) {
                    const uint32_t bro = nt ? browt1 : browt0;
                    ldsm4(bh[nt], sBhi + bro + ((ub ^ swb) << 4));
                    ldsm4(bl[nt], sBlo + bro + ((ub ^ swb) << 4));
                }
#pragma unroll
                for (int hf = 0; hf < 2; hf++) {
                    uint32_t ah[2][4], al[2][4];
                    const uint32_t ua = (uint32_t)(kb2 * 4 + hf * 2 + ua_lo);
                    const uint32_t au = (ua ^ swa) << 4;
#pragma unroll
                    for (int mt = 0; mt < 2; mt++) {
                        const uint32_t aro = mt ? arowt1 : arowt0;
                        ldsm4(ah[mt], sA + aro + au);
                        ldsm4(al[mt], sA + 8192 + aro + au);
                    }
#pragma unroll
                    for (int mt = 0; mt < 2; mt++)
#pragma unroll
                        for (int nt = 0; nt < 2; nt++) {
                            mma16816(acc[mt][nt], ah[mt],
                                     bh[nt][hf * 2], bh[nt][hf * 2 + 1]);
                            mma16816(acc[mt][nt], ah[mt],
                                     bl[nt][hf * 2], bl[nt][hf * 2 + 1]);
                            mma16816(acc[mt][nt], al[mt],
                                     bh[nt][hf * 2], bh[nt][hf * 2 + 1]);
                        }
                }
            }
        }

        // epilogue: + XW[t], tanh, split to bf16 hi/lo, store
        __nv_bfloat16* __restrict__ oh = g_hhi[pin ^ 1];
        __nv_bfloat16* __restrict__ ol = g_hlo[pin ^ 1];
#pragma unroll
        for (int mt = 0; mt < 2; mt++)
#pragma unroll
            for (int nt = 0; nt < 2; nt++) {
                const int cidx = col0 + wn + nt * 8 + (lane & 3) * 2;
#pragma unroll
                for (int h8 = 0; h8 < 2; h8++) {
                    const int r = row0 + wm + mt * 16 + (lane >> 2) + h8 * 8;
                    const float v0 = tanhf(acc[mt][nt][h8 * 2 + 0] + xwv[mt][nt][h8].x);
                    const float v1 = tanhf(acc[mt][nt][h8 * 2 + 1] + xwv[mt][nt][h8].y);
                    const float q0 = __bfloat162float(__float2bfloat16(v0));
                    const float q1 = __bfloat162float(__float2bfloat16(v1));
                    *reinterpret_cast<uint32_t*>(&oh[(size_t)r * H_DIM + cidx]) =
                        pack2bf(v0, v1);
                    *reinterpret_cast<uint32_t*>(&ol[(size_t)r * H_DIM + cidx]) =
                        pack2bf(v0 - q0, v1 - q1);
                }
            }

        if (t < T_SEQ - 1) {
            __threadfence();
            __syncthreads();
            if (tid == 0) atomicAdd(&g_bar[rg], 1);
        }
    }
}

// ---------------------------------------------------------------------------
// Final Dense(1): out[b] = (hhi+hlo)[0][b,:] . Wd + bd
// ---------------------------------------------------------------------------
__global__ __launch_bounds__(256) void final_dense_kernel(
    const float* __restrict__ Wd, const float* __restrict__ bd,
    float* __restrict__ out)
{
    __shared__ float red[256];
    const int b = blockIdx.x, tid = threadIdx.x;
    float s = 0.0f;
#pragma unroll
    for (int i = tid; i < H_DIM; i += 256) {
        const float h = __bfloat162float(g_hhi[0][(size_t)b * H_DIM + i])
                      + __bfloat162float(g_hlo[0][(size_t)b * H_DIM + i]);
        s += h * Wd[i];
    }
    red[tid] = s;
    __syncthreads();
    for (int off = 128; off > 0; off >>= 1) {
        if (tid < off) red[tid] += red[tid + off];
        __syncthreads();
    }
    if (tid == 0) out[b] = red[0] + bd[0];
}

// ---------------------------------------------------------------------------
extern "C" void kernel_launch(void* const* d_in, const int* in_sizes, int n_in,
                              void* d_out, int out_size)
{
    const float* x    = (const float*)d_in[0];   // [512, 256, 512]
    const float* W    = (const float*)d_in[1];   // [512, 1024]
    const float* U    = (const float*)d_in[2];   // [1024, 1024]
    const float* bias = (const float*)d_in[3];   // [1024]
    const float* Wd   = (const float*)d_in[4];   // [1024, 1]
    const float* bd   = (const float*)d_in[5];   // [1]
    float* out        = (float*)d_out;           // [512, 1]

    cudaFuncSetAttribute(xw_kernel,
                         cudaFuncAttributeMaxDynamicSharedMemorySize, PSMEM);
    cudaFuncSetAttribute(rnn_persist_kernel,
                         cudaFuncAttributeMaxDynamicSharedMemorySize, SMEM_P);

    // prep: transposed+split weights, zero h0 + barriers
    transpose_split_kernel<<<dim3(D_IN / 32, H_DIM / 32), 256>>>(W, D_IN, 0);
    transpose_split_kernel<<<dim3(H_DIM / 32, H_DIM / 32), 256>>>(U, H_DIM, 1);
    zero_h_kernel<<<256, 256>>>();

    // XW = x @ W + b  (one big parallel tensor GEMM)
    xw_kernel<<<(B_BATCH * T_SEQ) / 64, 256, PSMEM>>>(x, bias);

    // all 256 recurrent steps in ONE persistent launch
    rnn_persist_kernel<<<128, 256, SMEM_P>>>();

    final_dense_kernel<<<B_BATCH, 256>>>(Wd, bd, out);
}